// round 1
// baseline (speedup 1.0000x reference)
#include <cuda_runtime.h>
#include <math.h>

#define IN_DIM   8192
#define OUT_DIM  8192
#define BATCH    8192
#define ROWS     4           // batch rows staged per block
#define THREADS  1024

// GATE_COEFFS, 16 x 4
__constant__ float GC[16][4] = {
    {0, 0, 0, 0}, {0, 0, 0, 1}, {0, 1, 0, -1}, {0, 1, 0, 0},
    {0, 0, 1, -1}, {0, 0, 1, 0}, {0, 1, 1, -2}, {0, 1, 1, -1},
    {1, -1, -1, 1}, {1, -1, -1, 2}, {1, 0, -1, 0}, {1, 0, -1, 1},
    {1, -1, 0, 0}, {1, -1, 0, 1}, {1, 0, 0, -1}, {1, 0, 0, 0}
};

// Precomputed per-output-column params (written each launch -> deterministic)
__device__ float4 g_P[OUT_DIM];   // c0, c1, c2, c3
__device__ int2   g_I[OUT_DIM];   // idx_a, idx_b

__global__ void precompute_params(const float* __restrict__ weight,
                                  const int* __restrict__ idx_a,
                                  const int* __restrict__ idx_b) {
    int j = blockIdx.x * blockDim.x + threadIdx.x;
    if (j >= OUT_DIM) return;

    float v[16];
    float m = -INFINITY;
#pragma unroll
    for (int k = 0; k < 16; k++) {
        v[k] = weight[j * 16 + k];      // TAU = 1.0
        m = fmaxf(m, v[k]);
    }
    float s = 0.0f;
#pragma unroll
    for (int k = 0; k < 16; k++) {
        v[k] = expf(v[k] - m);
        s += v[k];
    }
    float inv = 1.0f / s;
    float c0 = 0.f, c1 = 0.f, c2 = 0.f, c3 = 0.f;
#pragma unroll
    for (int k = 0; k < 16; k++) {
        float w = v[k] * inv;
        c0 = fmaf(w, GC[k][0], c0);
        c1 = fmaf(w, GC[k][1], c1);
        c2 = fmaf(w, GC[k][2], c2);
        c3 = fmaf(w, GC[k][3], c3);
    }
    g_P[j] = make_float4(c0, c1, c2, c3);
    g_I[j] = make_int2(idx_a[j], idx_b[j]);
}

extern __shared__ float srow[];   // ROWS * IN_DIM floats = 128 KB

__global__ void __launch_bounds__(THREADS, 1)
logic_dense_kernel(const float* __restrict__ x,
                   float* __restrict__ out) {
    const int row0 = blockIdx.x * ROWS;

    // Stage ROWS contiguous x rows into shared memory (coalesced float4)
    const float4* __restrict__ x4 = reinterpret_cast<const float4*>(
        x + (size_t)row0 * IN_DIM);
    float4* s4 = reinterpret_cast<float4*>(srow);
    constexpr int N4 = ROWS * IN_DIM / 4;   // 8192
#pragma unroll
    for (int i = threadIdx.x; i < N4; i += THREADS)
        s4[i] = x4[i];
    __syncthreads();

    // Each thread handles OUT_DIM/THREADS = 8 columns
    for (int j = threadIdx.x; j < OUT_DIM; j += THREADS) {
        const float4 c = g_P[j];
        const int2  id = g_I[j];
#pragma unroll
        for (int r = 0; r < ROWS; r++) {
            const float a = srow[r * IN_DIM + id.x];
            const float b = srow[r * IN_DIM + id.y];
            float v = fmaf(c.y, a, c.x);
            v = fmaf(c.z, b, v);
            v = fmaf(c.w, a * b, v);
            out[(size_t)(row0 + r) * OUT_DIM + j] = v;
        }
    }
}

extern "C" void kernel_launch(void* const* d_in, const int* in_sizes, int n_in,
                              void* d_out, int out_size) {
    const float* x      = (const float*)d_in[0];
    const float* weight = (const float*)d_in[1];
    const int*   idx_a  = (const int*)d_in[2];
    const int*   idx_b  = (const int*)d_in[3];
    float*       out    = (float*)d_out;

    (void)in_sizes; (void)n_in; (void)out_size;

    precompute_params<<<OUT_DIM / 256, 256>>>(weight, idx_a, idx_b);

    const int smem_bytes = ROWS * IN_DIM * (int)sizeof(float);   // 131072
    cudaFuncSetAttribute(logic_dense_kernel,
                         cudaFuncAttributeMaxDynamicSharedMemorySize,
                         smem_bytes);
    logic_dense_kernel<<<BATCH / ROWS, THREADS, smem_bytes>>>(x, out);
}

// round 2
// speedup vs baseline: 1.3331x; 1.3331x over previous
#include <cuda_runtime.h>
#include <math.h>

#define IN_DIM   8192
#define OUT_DIM  8192
#define BATCH    8192
#define ROWS     2            // batch rows per tile
#define NBUF     2
#define THREADS  1024
#define COLS_PT  (OUT_DIM / THREADS)   // 8 columns per thread
#define GRID     152          // one persistent CTA per GB300 SM

// GATE_COEFFS, 16 x 4
__constant__ float GC[16][4] = {
    {0, 0, 0, 0}, {0, 0, 0, 1}, {0, 1, 0, -1}, {0, 1, 0, 0},
    {0, 0, 1, -1}, {0, 0, 1, 0}, {0, 1, 1, -2}, {0, 1, 1, -1},
    {1, -1, -1, 1}, {1, -1, -1, 2}, {1, 0, -1, 0}, {1, 0, -1, 1},
    {1, -1, 0, 0}, {1, -1, 0, 1}, {1, 0, 0, -1}, {1, 0, 0, 0}
};

// Per-output-column params, written every launch (deterministic)
__device__ float4   g_P[OUT_DIM];    // c0, c1, c2, c3
__device__ unsigned g_I[OUT_DIM];    // idx_a | (idx_b << 13)

__global__ void precompute_params(const float* __restrict__ weight,
                                  const int* __restrict__ idx_a,
                                  const int* __restrict__ idx_b) {
    int j = blockIdx.x * blockDim.x + threadIdx.x;
    if (j >= OUT_DIM) return;

    float v[16];
    float m = -INFINITY;
#pragma unroll
    for (int k = 0; k < 16; k++) {
        v[k] = weight[j * 16 + k];     // TAU = 1.0
        m = fmaxf(m, v[k]);
    }
    float s = 0.0f;
#pragma unroll
    for (int k = 0; k < 16; k++) {
        v[k] = expf(v[k] - m);
        s += v[k];
    }
    float inv = 1.0f / s;
    float c0 = 0.f, c1 = 0.f, c2 = 0.f, c3 = 0.f;
#pragma unroll
    for (int k = 0; k < 16; k++) {
        float w = v[k] * inv;
        c0 = fmaf(w, GC[k][0], c0);
        c1 = fmaf(w, GC[k][1], c1);
        c2 = fmaf(w, GC[k][2], c2);
        c3 = fmaf(w, GC[k][3], c3);
    }
    g_P[j] = make_float4(c0, c1, c2, c3);
    g_I[j] = (unsigned)idx_a[j] | ((unsigned)idx_b[j] << 13);
}

extern __shared__ float smem[];   // NBUF * ROWS * IN_DIM floats = 128 KB

__device__ __forceinline__ void stage_tile(int buf, int tile,
                                           const float* __restrict__ x) {
    // Copy ROWS contiguous x rows (64 KB) into smem buffer via cp.async.
    const char* src = (const char*)(x + (size_t)tile * ROWS * IN_DIM);
    unsigned dst = (unsigned)__cvta_generic_to_shared(
        smem + buf * (ROWS * IN_DIM));
    constexpr int CP = ROWS * IN_DIM * 4 / 16 / THREADS;   // 4
#pragma unroll
    for (int i = 0; i < CP; i++) {
        int off = (threadIdx.x + i * THREADS) * 16;
        asm volatile("cp.async.cg.shared.global [%0], [%1], 16;\n"
                     :: "r"(dst + off), "l"(src + off));
    }
}

__global__ void __launch_bounds__(THREADS, 1)
logic_dense_kernel(const float* __restrict__ x,
                   float* __restrict__ out) {
    // Cache this thread's 8 columns' params in registers (loaded once).
    float4   c[COLS_PT];
    unsigned id[COLS_PT];
#pragma unroll
    for (int u = 0; u < COLS_PT; u++) {
        int j = threadIdx.x + u * THREADS;
        c[u]  = g_P[j];
        id[u] = g_I[j];
    }

    constexpr int NT = BATCH / ROWS;   // 4096 tiles

    // Prologue: stage first tile into buffer 0.
    int t0 = blockIdx.x;
    if (t0 < NT) {
        stage_tile(0, t0, x);
    }
    asm volatile("cp.async.commit_group;\n");

    int k = 0;
    for (int t = t0; t < NT; t += GRID, k++) {
        int tn = t + GRID;
        if (tn < NT) stage_tile((k + 1) & 1, tn, x);
        asm volatile("cp.async.commit_group;\n");
        asm volatile("cp.async.wait_group 1;\n");   // current tile's data ready
        __syncthreads();

        const float* __restrict__ buf = smem + (k & 1) * (ROWS * IN_DIM);
        float* __restrict__ outr = out + (size_t)t * ROWS * OUT_DIM;

#pragma unroll
        for (int u = 0; u < COLS_PT; u++) {
            const int j  = threadIdx.x + u * THREADS;
            const int ia = id[u] & 0x1FFF;
            const int ib = id[u] >> 13;
#pragma unroll
            for (int r = 0; r < ROWS; r++) {
                const float a = buf[r * IN_DIM + ia];
                const float b = buf[r * IN_DIM + ib];
                float v = fmaf(c[u].y, a, c[u].x);
                v = fmaf(c[u].z, b, v);
                v = fmaf(c[u].w, a * b, v);
                outr[r * OUT_DIM + j] = v;
            }
        }
        __syncthreads();   // everyone done with buf before it is restaged
    }
}

extern "C" void kernel_launch(void* const* d_in, const int* in_sizes, int n_in,
                              void* d_out, int out_size) {
    const float* x      = (const float*)d_in[0];
    const float* weight = (const float*)d_in[1];
    const int*   idx_a  = (const int*)d_in[2];
    const int*   idx_b  = (const int*)d_in[3];
    float*       out    = (float*)d_out;

    (void)in_sizes; (void)n_in; (void)out_size;

    precompute_params<<<OUT_DIM / 256, 256>>>(weight, idx_a, idx_b);

    const int smem_bytes = NBUF * ROWS * IN_DIM * (int)sizeof(float);  // 131072
    cudaFuncSetAttribute(logic_dense_kernel,
                         cudaFuncAttributeMaxDynamicSharedMemorySize,
                         smem_bytes);
    logic_dense_kernel<<<GRID, THREADS, smem_bytes>>>(x, out);
}